// round 12
// baseline (speedup 1.0000x reference)
#include <cuda_runtime.h>

#define TT   1024
#define BB   16
#define CC   1024
#define HH   16
#define KW   7
#define PADL 6
#define MM   (TT * BB)       // 16384
#define NN   (HH * KW)       // 112
#define KD   1024

#define BM 128
#define BK 32
#define NTILE (KD / BK)                             // 32
#define GEMM_BLOCKS (MM / BM)                       // 128
#define DENSE_BYTES ((size_t)BB * HH * TT * TT * 4) // 1 GiB

#define ASTR 132                  // floats per p-row (16B-aligned LDS128)
#define BSTR 33                   // ulls per o-row (conflict-free LDS64)
#define SMEM_A (BK * ASTR)        // 4224 floats per buffer
#define SMEM_B (NN * BSTR)        // 3696 ulls per buffer
#define DYN_BYTES (2 * SMEM_A * 4 + 2 * SMEM_B * 8)   // 92928 B

// softmaxed conv weights, [m = t*16+b][o = h*7+k]
__device__ float g_wsm[(size_t)MM * NN];

typedef unsigned long long ull;
__device__ __forceinline__ ull pk2(float lo, float hi) {
    ull r; asm("mov.b64 %0,{%1,%2};" : "=l"(r) : "f"(lo), "f"(hi)); return r;
}
__device__ __forceinline__ void upk2(ull v, float& lo, float& hi) {
    asm("mov.b64 {%0,%1},%2;" : "=f"(lo), "=f"(hi) : "l"(v));
}
__device__ __forceinline__ void fma2(ull& d, ull a, ull b) {
    asm("fma.rn.f32x2 %0,%1,%2,%3;" : "=l"(d) : "l"(a), "l"(b), "l"(d));
}
__device__ __forceinline__ ull add2(ull a, ull b) {
    ull r; asm("add.rn.f32x2 %0,%1,%2;" : "=l"(r) : "l"(a), "l"(b)); return r;
}

// ---------------------------------------------------------------------------
// GEMM  w = x @ W^T (16384 x 112 x 1024) + masked softmax over K=7 -> g_wsm
// 512 threads, split-K within the block (half-warps on p 0..15 / 16..31),
// DOUBLE-BUFFERED smem tiles: one __syncthreads per k-tile, STS overlaps
// compute of the other buffer.
// ---------------------------------------------------------------------------
__global__ __launch_bounds__(512)
void k_gemm_softmax(const float* __restrict__ x,
                    const float* __restrict__ W)
{
    extern __shared__ __align__(16) char dyn[];
    float* Asf[2] = { (float*)dyn, (float*)dyn + SMEM_A };
    ull*   Bsd[2] = { (ull*)(dyn + 2 * SMEM_A * 4),
                      (ull*)(dyn + 2 * SMEM_A * 4) + SMEM_B };

    const int tid   = threadIdx.x;
    const int htid  = tid & 255;
    const int tx    = htid & 15;     // head
    const int ty    = htid >> 4;     // 0..15, rows 8ty..8ty+7
    const int ph    = tid >> 8;      // p-half
    const int p0    = ph * 16;
    const int mBase = blockIdx.x * BM;

    const int kk  = tid & 31;        // loader column
    const int ldr = tid >> 5;        // loader row phase 0..15

    const float* pa = x + (size_t)(mBase + ldr) * KD + kk;
    const float* pb = W + (size_t)ldr * KD + kk;

    ull acc[7][4];
#pragma unroll
    for (int j = 0; j < 7; j++)
#pragma unroll
        for (int r = 0; r < 4; r++) acc[j][r] = 0ull;

    float aReg[8], bReg[7];

    // prologue: tile 0 -> buffer 0
#pragma unroll
    for (int rr = 0; rr < 8; rr++) aReg[rr] = pa[rr * 16 * KD];
#pragma unroll
    for (int oo = 0; oo < 7; oo++) bReg[oo] = pb[oo * 16 * KD];
#pragma unroll
    for (int rr = 0; rr < 8; rr++) Asf[0][kk * ASTR + ldr + rr * 16] = aReg[rr];
#pragma unroll
    for (int oo = 0; oo < 7; oo++) Bsd[0][(ldr + oo * 16) * BSTR + kk] = pk2(bReg[oo], bReg[oo]);
    __syncthreads();

    for (int kt = 0; kt < NTILE; kt++) {
        const int buf = kt & 1;
        if (kt + 1 < NTILE) {
            const int k0 = (kt + 1) * BK;
#pragma unroll
            for (int rr = 0; rr < 8; rr++) aReg[rr] = pa[rr * 16 * KD + k0];
#pragma unroll
            for (int oo = 0; oo < 7; oo++) bReg[oo] = pb[oo * 16 * KD + k0];
        }

        const float* Ab = Asf[buf];
        const ull*   Bb = Bsd[buf] + tx * 7 * BSTR;
#pragma unroll 4
        for (int pp = 0; pp < 16; pp++) {
            const int p = p0 + pp;
            const ulonglong2* ap = (const ulonglong2*)&Ab[p * ASTR + 8 * ty];
            ulonglong2 A0 = ap[0];       // rows (0,1),(2,3)
            ulonglong2 A1 = ap[1];       // rows (4,5),(6,7)
#pragma unroll
            for (int j = 0; j < 7; j++) {
                ull bb = Bb[j * BSTR + p];
                fma2(acc[j][0], A0.x, bb);
                fma2(acc[j][1], A0.y, bb);
                fma2(acc[j][2], A1.x, bb);
                fma2(acc[j][3], A1.y, bb);
            }
        }

        if (kt + 1 < NTILE) {
            const int nb = buf ^ 1;
#pragma unroll
            for (int rr = 0; rr < 8; rr++) Asf[nb][kk * ASTR + ldr + rr * 16] = aReg[rr];
#pragma unroll
            for (int oo = 0; oo < 7; oo++) Bsd[nb][(ldr + oo * 16) * BSTR + kk] = pk2(bReg[oo], bReg[oo]);
        }
        __syncthreads();
    }

    // ---- cross-half reduction through smem (reuse buffer region) ----
    ull* xch = (ull*)dyn;            // 28672 B needed, buffers done after sync
#pragma unroll
    for (int c = 0; c < 2; c++) {
        if (ph == 1) {
#pragma unroll
            for (int j = 0; j < 7; j++) {
                xch[htid * 14 + j * 2 + 0] = acc[j][2 * c + 0];
                xch[htid * 14 + j * 2 + 1] = acc[j][2 * c + 1];
            }
        }
        __syncthreads();
        if (ph == 0) {
#pragma unroll
            for (int j = 0; j < 7; j++) {
                acc[j][2 * c + 0] = add2(acc[j][2 * c + 0], xch[htid * 14 + j * 2 + 0]);
                acc[j][2 * c + 1] = add2(acc[j][2 * c + 1], xch[htid * 14 + j * 2 + 1]);
            }
        }
        __syncthreads();
    }

    if (ph == 1) return;

    // ---- masked softmax over K=7 for this thread's 8 rows, head tx ----
#pragma unroll
    for (int rp = 0; rp < 4; rp++) {
        float f0[7], f1[7];
#pragma unroll
        for (int j = 0; j < 7; j++) upk2(acc[j][rp], f0[j], f1[j]);

#pragma unroll
        for (int half = 0; half < 2; half++) {
            float* f = half ? f1 : f0;
            int m = mBase + ty * 8 + rp * 2 + half;
            int t = m >> 4;
            int kmin = PADL - t; if (kmin < 0) kmin = 0;

            float mx = -1e30f;
#pragma unroll
            for (int k = 0; k < 7; k++)
                if (k >= kmin && f[k] > mx) mx = f[k];

            float e[7], s = 0.f;
#pragma unroll
            for (int k = 0; k < 7; k++) {
                e[k] = (k >= kmin) ? __expf(f[k] - mx) : 0.f;
                s += e[k];
            }
            float inv = 1.f / s;
            float* gp = &g_wsm[(size_t)m * NN + tx * 7];
#pragma unroll
            for (int k = 0; k < 7; k++)
                gp[k] = e[k] * inv;
        }
    }
}

// ---------------------------------------------------------------------------
// k_out_band: eight consecutive t per block; 14 gather loads feed 8 outputs,
// plus the band scatter for those 8 rows (dense already zeroed by memset).
// ---------------------------------------------------------------------------
__global__ __launch_bounds__(256)
void k_out_band(const float* __restrict__ x,
                float* __restrict__ out,
                float* __restrict__ dense)
{
    const int t0  = blockIdx.x * 8;
    const int b   = blockIdx.y;
    const int tid = threadIdx.x;

    __shared__ float sw[8 * NN];
    for (int e = tid; e < 8 * NN; e += 256) {
        int r = e / NN, idx = e - r * NN;
        sw[e] = g_wsm[(size_t)((t0 + r) * BB + b) * NN + idx];
    }
    __syncthreads();

    const int h = tid >> 4;
    const float4* x4 = (const float4*)x;

    float4 v[14];
#pragma unroll
    for (int k = 0; k < 14; k++) {
        int pos = t0 - PADL + k;
        if (pos < 0) pos = 0;               // weight is exactly 0 there
        v[k] = x4[((size_t)(pos * BB + b) << 8) + tid];
    }

    float4* out4 = (float4*)out;
#pragma unroll
    for (int r = 0; r < 8; r++) {
        const float* wr = &sw[r * NN + h * 7];
        float4 a = make_float4(0.f, 0.f, 0.f, 0.f);
#pragma unroll
        for (int k = 0; k < 7; k++) {
            float wk = wr[k];
            a.x += wk * v[r + k].x;
            a.y += wk * v[r + k].y;
            a.z += wk * v[r + k].z;
            a.w += wk * v[r + k].w;
        }
        out4[((size_t)((t0 + r) * BB + b) << 8) + tid] = a;
    }

    // band scatter for the 8 rows (zeros already laid by memset)
    for (int e = tid; e < 8 * NN; e += 256) {
        int r   = e / NN, idx = e - r * NN;
        int hh  = idx / 7;
        int k   = idx - hh * 7;
        int t   = t0 + r;
        int col = t - PADL + k;
        if (col >= 0)
            dense[((size_t)(b * HH + hh) << 20) + ((size_t)t << 10) + col] = sw[e];
    }
}

// ---------------------------------------------------------------------------
// Serial: gemm -> memset(dense) -> k_out_band.
// ---------------------------------------------------------------------------
extern "C" void kernel_launch(void* const* d_in, const int* in_sizes, int n_in,
                              void* d_out, int out_size)
{
    const float* x = (const float*)d_in[0];   // (T, B, C) fp32
    const float* W = (const float*)d_in[1];   // (H*K, C)  fp32
    float* out   = (float*)d_out;
    float* dense = out + (size_t)MM * CC;

    cudaFuncSetAttribute(k_gemm_softmax,
                         cudaFuncAttributeMaxDynamicSharedMemorySize, DYN_BYTES);

    k_gemm_softmax<<<GEMM_BLOCKS, 512, DYN_BYTES>>>(x, W);
    cudaMemsetAsync(dense, 0, DENSE_BYTES);
    dim3 g2(TT / 8, BB);
    k_out_band<<<g2, 256>>>(x, out, dense);
}

// round 13
// speedup vs baseline: 1.0777x; 1.0777x over previous
#include <cuda_runtime.h>

#define TT   1024
#define BB   16
#define CC   1024
#define HH   16
#define KW   7
#define PADL 6
#define MM   (TT * BB)       // 16384
#define NN   (HH * KW)       // 112
#define KD   1024

#define BM 64
#define BK 32
#define NTILE (KD / BK)                             // 32
#define GEMM_BLOCKS (MM / BM)                       // 256
#define DENSE_BYTES ((size_t)BB * HH * TT * TT * 4) // 1 GiB

#define ASTR 66       // floats per p-row of A tile (8B-aligned 8ty offsets)
#define BSTR 33       // ulls per o-row of B tile (14*tx mod 32: conflict-free)

// softmaxed conv weights, [m = t*16+b][o = h*7+k]
__device__ float g_wsm[(size_t)MM * NN];

typedef unsigned long long ull;
__device__ __forceinline__ ull pk2(float lo, float hi) {
    ull r; asm("mov.b64 %0,{%1,%2};" : "=l"(r) : "f"(lo), "f"(hi)); return r;
}
__device__ __forceinline__ void upk2(ull v, float& lo, float& hi) {
    asm("mov.b64 {%0,%1},%2;" : "=f"(lo), "=f"(hi) : "l"(v));
}
__device__ __forceinline__ void fma2(ull& d, ull a, ull b) {
    asm("fma.rn.f32x2 %0,%1,%2,%3;" : "=l"(d) : "l"(a), "l"(b), "l"(d));
}

// ---------------------------------------------------------------------------
// GEMM  w = x @ W^T (16384 x 112 x 1024) + masked softmax over K=7 -> g_wsm
// BM=64, 128 threads, 8 rows/thread, software-pipelined — 38 KB smem/block
// so TWO blocks co-reside per SM; inter-block overlap hides each block's
// __syncthreads bubbles.
// ---------------------------------------------------------------------------
__global__ __launch_bounds__(128)
void k_gemm_softmax(const float* __restrict__ x,
                    const float* __restrict__ W)
{
    __shared__ __align__(16) float Asf[BK * ASTR];   //  8448 B, [p][m]
    __shared__ __align__(16) ull   Bsd[NN * BSTR];   // 29568 B, [o][p] dup'd

    const int tid   = threadIdx.x;
    const int tx    = tid & 15;      // head
    const int ty    = tid >> 4;      // 0..7, rows 8ty..8ty+7
    const int mBase = blockIdx.x * BM;

    const int kk  = tid & 31;        // loader column
    const int ldr = tid >> 5;        // loader row phase 0..3

    const float* pa = x + (size_t)(mBase + ldr) * KD + kk;
    const float* pb = W + (size_t)ldr * KD + kk;

    ull acc[7][4];
#pragma unroll
    for (int j = 0; j < 7; j++)
#pragma unroll
        for (int r = 0; r < 4; r++) acc[j][r] = 0ull;

    float aReg[16], bReg[28];

    // prologue: tile 0
#pragma unroll
    for (int rr = 0; rr < 16; rr++) aReg[rr] = pa[rr * 4 * KD];
#pragma unroll
    for (int oo = 0; oo < 28; oo++) bReg[oo] = pb[oo * 4 * KD];
#pragma unroll
    for (int rr = 0; rr < 16; rr++) Asf[kk * ASTR + ldr + rr * 4] = aReg[rr];
#pragma unroll
    for (int oo = 0; oo < 28; oo++) Bsd[(ldr + oo * 4) * BSTR + kk] = pk2(bReg[oo], bReg[oo]);
    __syncthreads();

    for (int kt = 1; kt <= NTILE; kt++) {
        const int k0 = kt * BK;
        if (kt < NTILE) {
            // next tile's LDGs land during compute
#pragma unroll
            for (int rr = 0; rr < 16; rr++) aReg[rr] = pa[rr * 4 * KD + k0];
#pragma unroll
            for (int oo = 0; oo < 28; oo++) bReg[oo] = pb[oo * 4 * KD + k0];
        }

#pragma unroll 4
        for (int p = 0; p < BK; p++) {
            const float* ap = &Asf[p * ASTR + 8 * ty];
            ull a0 = *(const ull*)(ap + 0);
            ull a1 = *(const ull*)(ap + 2);
            ull a2 = *(const ull*)(ap + 4);
            ull a3 = *(const ull*)(ap + 6);
#pragma unroll
            for (int j = 0; j < 7; j++) {
                ull bb = Bsd[(tx * 7 + j) * BSTR + p];
                fma2(acc[j][0], a0, bb);
                fma2(acc[j][1], a1, bb);
                fma2(acc[j][2], a2, bb);
                fma2(acc[j][3], a3, bb);
            }
        }
        __syncthreads();

        if (kt < NTILE) {
#pragma unroll
            for (int rr = 0; rr < 16; rr++) Asf[kk * ASTR + ldr + rr * 4] = aReg[rr];
#pragma unroll
            for (int oo = 0; oo < 28; oo++) Bsd[(ldr + oo * 4) * BSTR + kk] = pk2(bReg[oo], bReg[oo]);
            __syncthreads();
        }
    }

    // ---- masked softmax over K=7 for this thread's 8 rows, head tx ----
#pragma unroll
    for (int rp = 0; rp < 4; rp++) {
        float f0[7], f1[7];
#pragma unroll
        for (int j = 0; j < 7; j++) upk2(acc[j][rp], f0[j], f1[j]);

#pragma unroll
        for (int half = 0; half < 2; half++) {
            float* f = half ? f1 : f0;
            int m = mBase + ty * 8 + rp * 2 + half;
            int t = m >> 4;
            int kmin = PADL - t; if (kmin < 0) kmin = 0;

            float mx = -1e30f;
#pragma unroll
            for (int k = 0; k < 7; k++)
                if (k >= kmin && f[k] > mx) mx = f[k];

            float e[7], s = 0.f;
#pragma unroll
            for (int k = 0; k < 7; k++) {
                e[k] = (k >= kmin) ? __expf(f[k] - mx) : 0.f;
                s += e[k];
            }
            float inv = 1.f / s;
            float* gp = &g_wsm[(size_t)m * NN + tx * 7];
#pragma unroll
            for (int k = 0; k < 7; k++)
                gp[k] = e[k] * inv;
        }
    }
}

// ---------------------------------------------------------------------------
// k_out_band: eight consecutive t per block; 14 gather loads feed 8 outputs,
// plus the band scatter for those rows (dense already zeroed by memset).
// ---------------------------------------------------------------------------
__global__ __launch_bounds__(256)
void k_out_band(const float* __restrict__ x,
                float* __restrict__ out,
                float* __restrict__ dense)
{
    const int t0  = blockIdx.x * 8;
    const int b   = blockIdx.y;
    const int tid = threadIdx.x;

    __shared__ float sw[8 * NN];
    for (int e = tid; e < 8 * NN; e += 256) {
        int r = e / NN, idx = e - r * NN;
        sw[e] = g_wsm[(size_t)((t0 + r) * BB + b) * NN + idx];
    }
    __syncthreads();

    const int h = tid >> 4;
    const float4* x4 = (const float4*)x;

    float4 v[14];
#pragma unroll
    for (int k = 0; k < 14; k++) {
        int pos = t0 - PADL + k;
        if (pos < 0) pos = 0;               // weight is exactly 0 there
        v[k] = x4[((size_t)(pos * BB + b) << 8) + tid];
    }

    float4* out4 = (float4*)out;
#pragma unroll
    for (int r = 0; r < 8; r++) {
        const float* wr = &sw[r * NN + h * 7];
        float4 a = make_float4(0.f, 0.f, 0.f, 0.f);
#pragma unroll
        for (int k = 0; k < 7; k++) {
            float wk = wr[k];
            a.x += wk * v[r + k].x;
            a.y += wk * v[r + k].y;
            a.z += wk * v[r + k].z;
            a.w += wk * v[r + k].w;
        }
        out4[((size_t)((t0 + r) * BB + b) << 8) + tid] = a;
    }

    // band scatter for the 8 rows (zeros already laid by memset)
    for (int e = tid; e < 8 * NN; e += 256) {
        int r   = e / NN, idx = e - r * NN;
        int hh  = idx / 7;
        int k   = idx - hh * 7;
        int t   = t0 + r;
        int col = t - PADL + k;
        if (col >= 0)
            dense[((size_t)(b * HH + hh) << 20) + ((size_t)t << 10) + col] = sw[e];
    }
}

// ---------------------------------------------------------------------------
// Serial: gemm -> memset(dense) -> k_out_band.
// ---------------------------------------------------------------------------
extern "C" void kernel_launch(void* const* d_in, const int* in_sizes, int n_in,
                              void* d_out, int out_size)
{
    const float* x = (const float*)d_in[0];   // (T, B, C) fp32
    const float* W = (const float*)d_in[1];   // (H*K, C)  fp32
    float* out   = (float*)d_out;
    float* dense = out + (size_t)MM * CC;

    k_gemm_softmax<<<GEMM_BLOCKS, 128>>>(x, W);
    cudaMemsetAsync(dense, 0, DENSE_BYTES);
    dim3 g2(TT / 8, BB);
    k_out_band<<<g2, 256>>>(x, out, dense);
}

// round 14
// speedup vs baseline: 1.0802x; 1.0023x over previous
#include <cuda_runtime.h>

#define TT   1024
#define BB   16
#define CC   1024
#define HH   16
#define KW   7
#define PADL 6
#define MM   (TT * BB)       // 16384
#define NN   (HH * KW)       // 112
#define KD   1024

#define BM 64
#define BK 32
#define KHALF 512
#define NTILE_H (KHALF / BK)                        // 16
#define MTILES  (MM / BM)                           // 256
#define DENSE_BYTES ((size_t)BB * HH * TT * TT * 4) // 1 GiB

#define ASTR 66       // floats per p-row of A tile
#define BSTR 33       // floats per o-row of B tile (bank 7tx+7j+p: conflict-free)

// partial logits per k-half, then softmaxed weights
__device__ float g_part[2][(size_t)MM * NN];
__device__ float g_wsm[(size_t)MM * NN];

typedef unsigned long long ull;
__device__ __forceinline__ ull pk2(float lo, float hi) {
    ull r; asm("mov.b64 %0,{%1,%2};" : "=l"(r) : "f"(lo), "f"(hi)); return r;
}
__device__ __forceinline__ void upk2(ull v, float& lo, float& hi) {
    asm("mov.b64 {%0,%1},%2;" : "=f"(lo), "=f"(hi) : "l"(v));
}
__device__ __forceinline__ void fma2(ull& d, ull a, ull b) {
    asm("fma.rn.f32x2 %0,%1,%2,%3;" : "=l"(d) : "l"(a), "l"(b), "l"(d));
}

// ---------------------------------------------------------------------------
// k_gemm_partial: grid (256, 2). Block (bx, ky) computes the K-half ky of
// rows [64*bx, 64*bx+64) x all 112 outputs -> g_part[ky].
// 128 threads, 8 rows/thread, software-pipelined, 23.2 KB smem
// -> 3-4 blocks/SM co-resident for latency cover.
// ---------------------------------------------------------------------------
__global__ __launch_bounds__(128, 4)
void k_gemm_partial(const float* __restrict__ x,
                    const float* __restrict__ W)
{
    __shared__ __align__(16) float Asf[BK * ASTR];   //  8448 B, [p][m]
    __shared__ __align__(16) float Bsf[NN * BSTR];   // 14784 B, [o][p]

    const int tid   = threadIdx.x;
    const int tx    = tid & 15;      // head
    const int ty    = tid >> 4;      // 0..7, rows 8ty..8ty+7
    const int mBase = blockIdx.x * BM;
    const int ky    = blockIdx.y;    // k-half
    const int kOff  = ky * KHALF;

    const int kk  = tid & 31;        // loader column
    const int ldr = tid >> 5;        // loader row phase 0..3

    const float* pa = x + (size_t)(mBase + ldr) * KD + kOff + kk;
    const float* pb = W + (size_t)ldr * KD + kOff + kk;

    ull acc[7][4];
#pragma unroll
    for (int j = 0; j < 7; j++)
#pragma unroll
        for (int r = 0; r < 4; r++) acc[j][r] = 0ull;

    float aReg[16], bReg[28];

    // prologue: tile 0
#pragma unroll
    for (int rr = 0; rr < 16; rr++) aReg[rr] = pa[rr * 4 * KD];
#pragma unroll
    for (int oo = 0; oo < 28; oo++) bReg[oo] = pb[oo * 4 * KD];
#pragma unroll
    for (int rr = 0; rr < 16; rr++) Asf[kk * ASTR + ldr + rr * 4] = aReg[rr];
#pragma unroll
    for (int oo = 0; oo < 28; oo++) Bsf[(ldr + oo * 4) * BSTR + kk] = bReg[oo];
    __syncthreads();

    for (int kt = 1; kt <= NTILE_H; kt++) {
        const int k0 = kt * BK;
        if (kt < NTILE_H) {
#pragma unroll
            for (int rr = 0; rr < 16; rr++) aReg[rr] = pa[rr * 4 * KD + k0];
#pragma unroll
            for (int oo = 0; oo < 28; oo++) bReg[oo] = pb[oo * 4 * KD + k0];
        }

#pragma unroll 4
        for (int p = 0; p < BK; p++) {
            const float* ap = &Asf[p * ASTR + 8 * ty];
            ull a0 = *(const ull*)(ap + 0);
            ull a1 = *(const ull*)(ap + 2);
            ull a2 = *(const ull*)(ap + 4);
            ull a3 = *(const ull*)(ap + 6);
#pragma unroll
            for (int j = 0; j < 7; j++) {
                float b = Bsf[(tx * 7 + j) * BSTR + p];
                ull bb = pk2(b, b);
                fma2(acc[j][0], a0, bb);
                fma2(acc[j][1], a1, bb);
                fma2(acc[j][2], a2, bb);
                fma2(acc[j][3], a3, bb);
            }
        }
        __syncthreads();

        if (kt < NTILE_H) {
#pragma unroll
            for (int rr = 0; rr < 16; rr++) Asf[kk * ASTR + ldr + rr * 4] = aReg[rr];
#pragma unroll
            for (int oo = 0; oo < 28; oo++) Bsf[(ldr + oo * 4) * BSTR + kk] = bReg[oo];
            __syncthreads();
        }
    }

    // store partial logits (no softmax here)
    float* gp0 = &g_part[ky][(size_t)(mBase + ty * 8) * NN + tx * 7];
#pragma unroll
    for (int rp = 0; rp < 4; rp++) {
        float f0[7], f1[7];
#pragma unroll
        for (int j = 0; j < 7; j++) upk2(acc[j][rp], f0[j], f1[j]);
        float* ga = gp0 + (size_t)(rp * 2 + 0) * NN;
        float* gb = gp0 + (size_t)(rp * 2 + 1) * NN;
#pragma unroll
        for (int k = 0; k < 7; k++) { ga[k] = f0[k]; gb[k] = f1[k]; }
    }
}

// ---------------------------------------------------------------------------
// k_reduce_softmax: one thread per (m, head). Sums the two K-half partials,
// applies the masked softmax over K=7, writes g_wsm.
// ---------------------------------------------------------------------------
__global__ __launch_bounds__(256)
void k_reduce_softmax()
{
    int gt = blockIdx.x * 256 + threadIdx.x;    // 0 .. MM*HH-1
    int m  = gt >> 4;
    int h  = gt & 15;
    int t  = m >> 4;

    const float* p0 = &g_part[0][(size_t)m * NN + h * 7];
    const float* p1 = &g_part[1][(size_t)m * NN + h * 7];

    float f[7];
#pragma unroll
    for (int k = 0; k < 7; k++) f[k] = p0[k] + p1[k];

    int kmin = PADL - t; if (kmin < 0) kmin = 0;

    float mx = -1e30f;
#pragma unroll
    for (int k = 0; k < 7; k++)
        if (k >= kmin && f[k] > mx) mx = f[k];

    float e[7], s = 0.f;
#pragma unroll
    for (int k = 0; k < 7; k++) {
        e[k] = (k >= kmin) ? __expf(f[k] - mx) : 0.f;
        s += e[k];
    }
    float inv = 1.f / s;
    float* gp = &g_wsm[(size_t)m * NN + h * 7];
#pragma unroll
    for (int k = 0; k < 7; k++)
        gp[k] = e[k] * inv;
}

// ---------------------------------------------------------------------------
// k_out_band: eight consecutive t per block; 14 gather loads feed 8 outputs,
// plus the band scatter for those rows (dense already zeroed by memset).
// ---------------------------------------------------------------------------
__global__ __launch_bounds__(256)
void k_out_band(const float* __restrict__ x,
                float* __restrict__ out,
                float* __restrict__ dense)
{
    const int t0  = blockIdx.x * 8;
    const int b   = blockIdx.y;
    const int tid = threadIdx.x;

    __shared__ float sw[8 * NN];
    for (int e = tid; e < 8 * NN; e += 256) {
        int r = e / NN, idx = e - r * NN;
        sw[e] = g_wsm[(size_t)((t0 + r) * BB + b) * NN + idx];
    }
    __syncthreads();

    const int h = tid >> 4;
    const float4* x4 = (const float4*)x;

    float4 v[14];
#pragma unroll
    for (int k = 0; k < 14; k++) {
        int pos = t0 - PADL + k;
        if (pos < 0) pos = 0;               // weight is exactly 0 there
        v[k] = x4[((size_t)(pos * BB + b) << 8) + tid];
    }

    float4* out4 = (float4*)out;
#pragma unroll
    for (int r = 0; r < 8; r++) {
        const float* wr = &sw[r * NN + h * 7];
        float4 a = make_float4(0.f, 0.f, 0.f, 0.f);
#pragma unroll
        for (int k = 0; k < 7; k++) {
            float wk = wr[k];
            a.x += wk * v[r + k].x;
            a.y += wk * v[r + k].y;
            a.z += wk * v[r + k].z;
            a.w += wk * v[r + k].w;
        }
        out4[((size_t)((t0 + r) * BB + b) << 8) + tid] = a;
    }

    // band scatter for the 8 rows (zeros already laid by memset)
    for (int e = tid; e < 8 * NN; e += 256) {
        int r   = e / NN, idx = e - r * NN;
        int hh  = idx / 7;
        int k   = idx - hh * 7;
        int t   = t0 + r;
        int col = t - PADL + k;
        if (col >= 0)
            dense[((size_t)(b * HH + hh) << 20) + ((size_t)t << 10) + col] = sw[e];
    }
}

// ---------------------------------------------------------------------------
// Serial: gemm_partial -> reduce_softmax -> memset(dense) -> k_out_band.
// ---------------------------------------------------------------------------
extern "C" void kernel_launch(void* const* d_in, const int* in_sizes, int n_in,
                              void* d_out, int out_size)
{
    const float* x = (const float*)d_in[0];   // (T, B, C) fp32
    const float* W = (const float*)d_in[1];   // (H*K, C)  fp32
    float* out   = (float*)d_out;
    float* dense = out + (size_t)MM * CC;

    dim3 gg(MTILES, 2);
    k_gemm_partial<<<gg, 128>>>(x, W);
    k_reduce_softmax<<<(MM * HH) / 256, 256>>>();
    cudaMemsetAsync(dense, 0, DENSE_BYTES);
    dim3 g2(TT / 8, BB);
    k_out_band<<<g2, 256>>>(x, out, dense);
}